// round 12
// baseline (speedup 1.0000x reference)
#include <cuda_runtime.h>
#include <cuda_bf16.h>

// BBAStar: 8-connected grid shortest path, B=128, 32x32.
// R11 hybrid: V phase = R3 band Gauss-Seidel (4-row bands, KP=2 fwd+bwd,
// shfl chains => vertical+diagonal reach ~8 rows/epoch). H phase = IN-LANE:
// 8 warps build pre[r][c] (exact min of the 6 vertical/diag neighbors) in
// parallel, then warp 0 (lane = row, row in registers) runs L->R and R->L
// GS sweeps at ~12 cyc/cell with FULL 32-column reach.
// All updates are fl(w + exact-min8) of monotone valid upper bounds =>
// bit-exact float fixed point of the reference's 1024 Jacobi sweeps.
// Zero-change epoch (V applies the full operator to every cell) => verified.
// Backtrack via precomputed argmin-neighbor linear deltas (exact OFFS
// first-occurrence tie-break).

#define BN 128
#define ST 35              // dist row stride (odd => conflict-free both axes)
#define INF_F 1000000000.0f
#define EPS_F 1e-6f
#define KP 2               // fwd+bwd sweep pairs in the V phase

__device__ __forceinline__ float shl(float v, int lane) {
    float t = __shfl_up_sync(0xffffffffu, v, 1);
    return (lane == 0) ? INF_F : t;
}
__device__ __forceinline__ float shr(float v, int lane) {
    float t = __shfl_down_sync(0xffffffffu, v, 1);
    return (lane == 31) ? INF_F : t;
}
__device__ __forceinline__ float min8f(float a, float b, float c, float d,
                                       float e, float f, float g, float h) {
    return fminf(fminf(fminf(a, b), fminf(c, d)),
                 fminf(fminf(e, f), fminf(g, h)));
}
// OFFS-order first-occurrence argmin; returns linear delta dr*32+dc.
__device__ __forceinline__ int pick8d(float a0, float a1, float a2, float a3,
                                      float a4, float a5, float a6, float a7) {
    float bb = a0; int bd = -33;
    if (a1 < bb) { bb = a1; bd = -32; }
    if (a2 < bb) { bb = a2; bd = -31; }
    if (a3 < bb) { bb = a3; bd = -1; }
    if (a4 < bb) { bb = a4; bd = 1; }
    if (a5 < bb) { bb = a5; bd = 31; }
    if (a6 < bb) { bb = a6; bd = 32; }
    if (a7 < bb) { bb = a7; bd = 33; }
    return bd;
}

// R3's V-band GS fwd+bwd sweep pair over 4 owned rows (diagonal-inclusive:
// freshly updated row is shfl'd before the next row).
__device__ __forceinline__ void sweep_pair_v(volatile float* vd, const float w[4],
                                             float d[4], int i0,
                                             int ix, int iy, int lane, bool& any)
{
    {   // forward (down)
        float X = vd[ix], Y = vd[iy];
        float p = X, pl = shl(X, lane), pr = shr(X, lane);
        #pragma unroll
        for (int i = 0; i < 4; ++i) {
            float nx = (i < 3) ? d[i + 1] : Y;
            float nl = shl(nx, lane), nr = shr(nx, lane);
            float cl = shl(d[i], lane), cr = shr(d[i], lane);
            float v = w[i] + min8f(pl, p, pr, cl, cr, nl, nx, nr);
            if (v < d[i]) { d[i] = v; vd[i0 + i * ST] = v; any = true; }
            p = d[i]; pl = shl(p, lane); pr = shr(p, lane);
        }
    }
    {   // backward (up)
        float X = vd[ix], Y = vd[iy];
        float p = Y, pl = shl(Y, lane), pr = shr(Y, lane);
        #pragma unroll
        for (int i = 3; i >= 0; --i) {
            float nx = (i > 0) ? d[i - 1] : X;
            float nl = shl(nx, lane), nr = shr(nx, lane);
            float cl = shl(d[i], lane), cr = shr(d[i], lane);
            float v = w[i] + min8f(nl, nx, nr, cl, cr, pl, p, pr);
            if (v < d[i]) { d[i] = v; vd[i0 + i * ST] = v; any = true; }
            p = d[i]; pl = shl(p, lane); pr = shr(p, lane);
        }
    }
}

__global__ void __launch_bounds__(256, 1)
bba_kernel(const float* __restrict__ weights,
           const int*   __restrict__ source,
           const int*   __restrict__ target,
           float*       __restrict__ out)
{
    __shared__ float dist[34 * ST];     // padded 34x34, stride 35
    __shared__ float wsh[32][33];       // weights (+EPS)
    __shared__ float pre[32][33];       // 6-neighbor vertical/diag mins
    __shared__ int   nbr[1024];         // backtrack linear deltas
    volatile float* vd = dist;

    const int b    = blockIdx.x;
    const int tid  = threadIdx.x;
    const int wpid = tid >> 5;          // warp id 0..7
    const int lane = tid & 31;
    const int r0   = 4 * wpid;          // V band first row

    // Zero poisoned output slice.
    #pragma unroll
    for (int i = 0; i < 4; ++i) out[(b << 10) + i * 256 + tid] = 0.0f;

    for (int i = tid; i < 34 * ST; i += 256) dist[i] = INF_F;

    // Weights (+EPS), coalesced; stash for row-layout reads.
    const float* wb = weights + (b << 10);
    float wv[4];
    #pragma unroll
    for (int i = 0; i < 4; ++i) {
        wv[i] = wb[((r0 + i) << 5) + lane] + EPS_F;
        wsh[r0 + i][lane] = wv[i];
    }

    const int sr = source[2 * b + 0];
    const int sc = source[2 * b + 1];
    const int tr = target[2 * b + 0];
    const int tc = target[2 * b + 1];

    __syncthreads();

    // Warp 0 preloads its whole row of weights for the in-lane H phase.
    float wrow[32];
    if (wpid == 0) {
        #pragma unroll
        for (int c = 0; c < 32; ++c) wrow[c] = wsh[lane][c];
    }
    if (tid == 0) dist[(sr + 1) * ST + (sc + 1)] = wsh[sr][sc];
    __syncthreads();

    const int v_i0 = (r0 + 1) * ST + (lane + 1);
    const int v_ix = (r0 + 0) * ST + (lane + 1);
    const int v_iy = (r0 + 5) * ST + (lane + 1);

    // Cells owned for the pre-build (4 per thread, row-major).
    int own[4];
    #pragma unroll
    for (int k = 0; k < 4; ++k) {
        int i = k * 256 + tid;
        own[k] = ((i >> 5) + 1) * ST + (i & 31) + 1;
    }

    float d[4];

    for (;;) {
        bool any = false;

        // ---- V phase: band GS, KP fwd+bwd pairs ----
        #pragma unroll
        for (int i = 0; i < 4; ++i) d[i] = vd[v_i0 + i * ST];
        #pragma unroll 1
        for (int k = 0; k < KP; ++k)
            sweep_pair_v(vd, wv, d, v_i0, v_ix, v_iy, lane, any);

        __syncthreads();                 // V writes visible for pre-build

        // ---- pre-build (all warps): exact min of 6 vertical/diag nbrs ----
        #pragma unroll
        for (int k = 0; k < 4; ++k) {
            const int u = own[k];
            const int i = k * 256 + tid;
            float m = fminf(fminf(fminf(dist[u - ST - 1], dist[u - ST]),
                                  fminf(dist[u - ST + 1], dist[u + ST - 1])),
                            fminf(dist[u + ST], dist[u + ST + 1]));
            pre[i >> 5][i & 31] = m;
        }
        __syncthreads();                 // pre visible to warp 0

        // ---- H phase (warp 0, in-lane, full horizontal reach) ----
        if (wpid == 0) {
            const int base = (lane + 1) * ST + 1;
            float dd[32];
            #pragma unroll
            for (int c = 0; c < 32; ++c) dd[c] = dist[base + c];
            // L -> R
            float left = INF_F;
            #pragma unroll
            for (int c = 0; c < 32; ++c) {
                float right = (c < 31) ? dd[c + 1] : INF_F;   // pre-update
                float x = fminf(pre[lane][c], fminf(left, right));
                float v = wrow[c] + x;
                if (v < dd[c]) { dd[c] = v; any = true; }
                left = dd[c];
            }
            // R -> L
            float rightA = INF_F;
            #pragma unroll
            for (int c = 31; c >= 0; --c) {
                float leftv = (c > 0) ? dd[c - 1] : INF_F;    // pre-update
                float x = fminf(pre[lane][c], fminf(leftv, rightA));
                float v = wrow[c] + x;
                if (v < dd[c]) { dd[c] = v; any = true; }
                rightA = dd[c];
            }
            #pragma unroll
            for (int c = 0; c < 32; ++c) dist[base + c] = dd[c];
        }

        if (!__syncthreads_or((int)any)) break;   // zero-change epoch => d*
    }

    // Parallel argmin-neighbor deltas (V layout), OFFS order:
    // (-1,-1),(-1,0),(-1,1),(0,-1),(0,1),(1,-1),(1,0),(1,1)
    {
        #pragma unroll
        for (int i = 0; i < 4; ++i) d[i] = vd[v_i0 + i * ST];
        float X  = vd[v_ix], Y = vd[v_iy];
        float XL = shl(X, lane),    XR = shr(X, lane);
        float L0 = shl(d[0], lane), R0 = shr(d[0], lane);
        float L1 = shl(d[1], lane), R1 = shr(d[1], lane);
        float L2 = shl(d[2], lane), R2 = shr(d[2], lane);
        float L3 = shl(d[3], lane), R3 = shr(d[3], lane);
        float YL = shl(Y, lane),    YR = shr(Y, lane);
        nbr[((r0 + 0) << 5) + lane] = pick8d(XL, X,    XR, L0, R0, L1, d[1], R1);
        nbr[((r0 + 1) << 5) + lane] = pick8d(L0, d[0], R0, L1, R1, L2, d[2], R2);
        nbr[((r0 + 2) << 5) + lane] = pick8d(L1, d[1], R1, L2, R2, L3, d[3], R3);
        nbr[((r0 + 3) << 5) + lane] = pick8d(L2, d[2], R2, L3, R3, YL, Y,    YR);
    }
    __syncthreads();

    // Serial backtrack: idx += nbr[idx] per step (LDS + IADD chain).
    if (tid == 0) {
        int idx = (tr << 5) + tc;
        const int sidx = (sr << 5) + sc;
        float* o = out + (b << 10);
        for (int step = 0; step < 1024; ++step) {
            o[idx] = 1.0f;
            if (idx == sidx) break;
            idx += nbr[idx];
        }
    }
}

extern "C" void kernel_launch(void* const* d_in, const int* in_sizes, int n_in,
                              void* d_out, int out_size)
{
    const float* weights = (const float*)d_in[0];
    const int*   source  = (const int*)d_in[1];
    const int*   target  = (const int*)d_in[2];
    float*       out     = (float*)d_out;

    bba_kernel<<<BN, 256>>>(weights, source, target, out);
}

// round 13
// speedup vs baseline: 1.1201x; 1.1201x over previous
#include <cuda_runtime.h>
#include <cuda_bf16.h>

// BBAStar: 8-connected grid shortest path, B=128, 32x32.
// R12 = R6 structure with KP=4 (amortize per-epoch overhead over more sweeps;
// model: total = C*(a/(4KP) + b/4), decreasing in KP) + delta-encoded backtrack.
// V phase: 4-row bands (lane=col), KP fwd+bwd diagonal-inclusive GS sweep
// pairs; H phase: 4-col bands (lane=row), same. One plain barrier between
// phases, one __syncthreads_or as convergence reduction.
// All updates are fl(w + exact-min8) on monotone valid upper bounds =>
// bit-exact float fixed point of the reference's 1024 Jacobi sweeps; a
// zero-change epoch (V applies the full operator to every cell) => verified.
// Backtrack follows precomputed argmin-neighbor LINEAR DELTAS (exact OFFS
// first-occurrence tie-break), LDS+IADD per step.

#define BN 128
#define ST 35              // smem row stride (odd => conflict-free both axes)
#define INF_F 1000000000.0f
#define EPS_F 1e-6f
#define KP 4               // fwd+bwd sweep pairs per phase

__device__ __forceinline__ float shl(float v, int lane) {
    float t = __shfl_up_sync(0xffffffffu, v, 1);
    return (lane == 0) ? INF_F : t;
}
__device__ __forceinline__ float shr(float v, int lane) {
    float t = __shfl_down_sync(0xffffffffu, v, 1);
    return (lane == 31) ? INF_F : t;
}
__device__ __forceinline__ float min8f(float a, float b, float c, float d,
                                       float e, float f, float g, float h) {
    return fminf(fminf(fminf(a, b), fminf(c, d)),
                 fminf(fminf(e, f), fminf(g, h)));
}
// OFFS-order first-occurrence argmin; returns linear delta dr*32+dc.
__device__ __forceinline__ int pick8d(float a0, float a1, float a2, float a3,
                                      float a4, float a5, float a6, float a7) {
    float bb = a0; int bd = -33;
    if (a1 < bb) { bb = a1; bd = -32; }
    if (a2 < bb) { bb = a2; bd = -31; }
    if (a3 < bb) { bb = a3; bd = -1; }
    if (a4 < bb) { bb = a4; bd = 1; }
    if (a5 < bb) { bb = a5; bd = 31; }
    if (a6 < bb) { bb = a6; bd = 32; }
    if (a7 < bb) { bb = a7; bd = 33; }
    return bd;
}

// Forward GS sweep over the 4 owned lines (fresh prev-line shfls on the
// diagonal chain; current-line shfls reused from previous line's next shfls).
__device__ __forceinline__ void sweep_fwd(volatile float* vd, const float w[4],
                                          float d[4], int i0, int di,
                                          int ix, int iy, int lane, bool& any)
{
    float X = vd[ix], Y = vd[iy];
    float p = X, pl = shl(X, lane), pr = shr(X, lane);
    float cl = shl(d[0], lane), cr = shr(d[0], lane);
    #pragma unroll
    for (int i = 0; i < 4; ++i) {
        float nx = (i < 3) ? d[i + 1] : Y;
        float nl = shl(nx, lane), nr = shr(nx, lane);
        float v = w[i] + min8f(pl, p, pr, cl, cr, nl, nx, nr);
        if (v < d[i]) { d[i] = v; vd[i0 + i * di] = v; any = true; }
        p = d[i]; pl = shl(p, lane); pr = shr(p, lane);
        cl = nl; cr = nr;
    }
}
// Backward GS sweep (mirror).
__device__ __forceinline__ void sweep_bwd(volatile float* vd, const float w[4],
                                          float d[4], int i0, int di,
                                          int ix, int iy, int lane, bool& any)
{
    float X = vd[ix], Y = vd[iy];
    float p = Y, pl = shl(Y, lane), pr = shr(Y, lane);
    float cl = shl(d[3], lane), cr = shr(d[3], lane);
    #pragma unroll
    for (int i = 3; i >= 0; --i) {
        float nx = (i > 0) ? d[i - 1] : X;
        float nl = shl(nx, lane), nr = shr(nx, lane);
        float v = w[i] + min8f(nl, nx, nr, cl, cr, pl, p, pr);
        if (v < d[i]) { d[i] = v; vd[i0 + i * di] = v; any = true; }
        p = d[i]; pl = shl(p, lane); pr = shr(p, lane);
        cl = nl; cr = nr;
    }
}

__global__ void __launch_bounds__(256, 1)
bba_kernel(const float* __restrict__ weights,
           const int*   __restrict__ source,
           const int*   __restrict__ target,
           float*       __restrict__ out)
{
    __shared__ float dist[34 * ST];     // padded 34x34, stride 35
    __shared__ float wsh[32][33];       // weights, conflict-free both axes
    __shared__ int   nbr[1024];         // backtrack linear deltas
    volatile float* vd = dist;

    const int b    = blockIdx.x;
    const int tid  = threadIdx.x;
    const int wpid = tid >> 5;          // warp id 0..7
    const int lane = tid & 31;
    const int r0   = 4 * wpid;          // V band first row
    const int c0   = 4 * wpid;          // H band first col

    // Weights first (DRAM latency on the critical path).
    const float* wb = weights + (b << 10);
    float wv[4], wh[4];
    #pragma unroll
    for (int i = 0; i < 4; ++i) wv[i] = wb[((r0 + i) << 5) + lane] + EPS_F;

    const int sr = source[2 * b + 0];
    const int sc = source[2 * b + 1];
    const int tr = target[2 * b + 0];
    const int tc = target[2 * b + 1];

    // Zero poisoned output slice (fire-and-forget STG).
    #pragma unroll
    for (int i = 0; i < 4; ++i) out[(b << 10) + i * 256 + tid] = 0.0f;

    for (int i = tid; i < 34 * ST; i += 256) dist[i] = INF_F;
    #pragma unroll
    for (int i = 0; i < 4; ++i) wsh[r0 + i][lane] = wv[i];
    __syncthreads();

    #pragma unroll
    for (int i = 0; i < 4; ++i) wh[i] = wsh[lane][c0 + i];
    if (tid == 0) dist[(sr + 1) * ST + (sc + 1)] = wsh[sr][sc];
    __syncthreads();

    const int v_i0 = (r0 + 1) * ST + (lane + 1);
    const int v_ix = (r0 + 0) * ST + (lane + 1);
    const int v_iy = (r0 + 5) * ST + (lane + 1);
    const int h_i0 = (lane + 1) * ST + (c0 + 1);
    const int h_ix = (lane + 1) * ST + (c0 + 0);
    const int h_iy = (lane + 1) * ST + (c0 + 5);

    float d[4];

    for (;;) {
        bool any = false;

        // V phase: reload own rows, KP fwd+bwd GS sweep pairs.
        #pragma unroll
        for (int i = 0; i < 4; ++i) d[i] = vd[v_i0 + i * ST];
        #pragma unroll 1
        for (int k = 0; k < KP; ++k) {
            sweep_fwd(vd, wv, d, v_i0, ST, v_ix, v_iy, lane, any);
            sweep_bwd(vd, wv, d, v_i0, ST, v_ix, v_iy, lane, any);
        }

        __syncthreads();                 // V writes visible to H phase

        // H phase: reload own cols, KP fwd+bwd GS sweep pairs.
        #pragma unroll
        for (int i = 0; i < 4; ++i) d[i] = vd[h_i0 + i];
        #pragma unroll 1
        for (int k = 0; k < KP; ++k) {
            sweep_fwd(vd, wh, d, h_i0, 1, h_ix, h_iy, lane, any);
            sweep_bwd(vd, wh, d, h_i0, 1, h_ix, h_iy, lane, any);
        }

        if (!__syncthreads_or((int)any)) break;   // zero-change epoch => d*
    }

    // Parallel argmin-neighbor deltas (V layout), OFFS order:
    // (-1,-1),(-1,0),(-1,1),(0,-1),(0,1),(1,-1),(1,0),(1,1)
    {
        #pragma unroll
        for (int i = 0; i < 4; ++i) d[i] = vd[v_i0 + i * ST];
        float X  = vd[v_ix], Y = vd[v_iy];
        float XL = shl(X, lane),    XR = shr(X, lane);
        float L0 = shl(d[0], lane), R0 = shr(d[0], lane);
        float L1 = shl(d[1], lane), R1 = shr(d[1], lane);
        float L2 = shl(d[2], lane), R2 = shr(d[2], lane);
        float L3 = shl(d[3], lane), R3 = shr(d[3], lane);
        float YL = shl(Y, lane),    YR = shr(Y, lane);
        nbr[((r0 + 0) << 5) + lane] = pick8d(XL, X,    XR, L0, R0, L1, d[1], R1);
        nbr[((r0 + 1) << 5) + lane] = pick8d(L0, d[0], R0, L1, R1, L2, d[2], R2);
        nbr[((r0 + 2) << 5) + lane] = pick8d(L1, d[1], R1, L2, R2, L3, d[3], R3);
        nbr[((r0 + 3) << 5) + lane] = pick8d(L2, d[2], R2, L3, R3, YL, Y,    YR);
    }
    __syncthreads();

    // Serial backtrack: idx += nbr[idx] per step (LDS + IADD chain).
    if (tid == 0) {
        int idx = (tr << 5) + tc;
        const int sidx = (sr << 5) + sc;
        float* o = out + (b << 10);
        for (int step = 0; step < 1024; ++step) {
            o[idx] = 1.0f;
            if (idx == sidx) break;
            idx += nbr[idx];
        }
    }
}

extern "C" void kernel_launch(void* const* d_in, const int* in_sizes, int n_in,
                              void* d_out, int out_size)
{
    const float* weights = (const float*)d_in[0];
    const int*   source  = (const int*)d_in[1];
    const int*   target  = (const int*)d_in[2];
    float*       out     = (float*)d_out;

    bba_kernel<<<BN, 256>>>(weights, source, target, out);
}

// round 14
// speedup vs baseline: 1.4206x; 1.2682x over previous
#include <cuda_runtime.h>
#include <cuda_bf16.h>

// BBAStar: 8-connected grid shortest path, B=128, 32x32.
// R13 = the measured-best Round-4 kernel (alternating V/H band Gauss-Seidel,
// KP=2 fwd+bwd sweep pairs per phase, 3-barrier convergence-flag protocol,
// fresh per-row shfls) with ONE change: the serial backtrack follows
// precomputed argmin-neighbor LINEAR DELTAS (LDS+IADD per step) instead of
// an 8-load min-tree per step.
// Monotone relaxation with the exact reference operator fl(w + exact-min8)
// => bit-exact float fixed point of the reference's 1024 Jacobi sweeps under
// any schedule; a zero-change epoch => fixed point verified. pick8d keeps
// jnp.argmin's first-occurrence (strict '<') OFFS-order tie-break.

#define BN 128
#define ST 35              // smem row stride (odd => conflict-free both axes)
#define INF_F 1000000000.0f
#define EPS_F 1e-6f
#define KP 2               // fwd+bwd sweep pairs per phase

__device__ __forceinline__ float shl(float v, int lane) {
    float t = __shfl_up_sync(0xffffffffu, v, 1);
    return (lane == 0) ? INF_F : t;
}
__device__ __forceinline__ float shr(float v, int lane) {
    float t = __shfl_down_sync(0xffffffffu, v, 1);
    return (lane == 31) ? INF_F : t;
}
__device__ __forceinline__ float min8f(float a, float b, float c, float d,
                                       float e, float f, float g, float h) {
    return fminf(fminf(fminf(a, b), fminf(c, d)),
                 fminf(fminf(e, f), fminf(g, h)));
}
// OFFS-order first-occurrence argmin; returns linear delta dr*32+dc.
__device__ __forceinline__ int pick8d(float a0, float a1, float a2, float a3,
                                      float a4, float a5, float a6, float a7) {
    float bb = a0; int bd = -33;
    if (a1 < bb) { bb = a1; bd = -32; }
    if (a2 < bb) { bb = a2; bd = -31; }
    if (a3 < bb) { bb = a3; bd = -1; }
    if (a4 < bb) { bb = a4; bd = 1; }
    if (a5 < bb) { bb = a5; bd = 31; }
    if (a6 < bb) { bb = a6; bd = 32; }
    if (a7 < bb) { bb = a7; bd = 33; }
    return bd;
}

// One GS fwd+bwd sweep pair over 4 owned cells per lane (Round-4 version:
// fresh shfls per row, diagonal-inclusive Gauss-Seidel).
__device__ __forceinline__ void sweep_pair(volatile float* vd,
                                           const float w[4], float d[4],
                                           int i0, int di, int ix, int iy,
                                           int lane, bool& any)
{
    // forward sweep
    {
        float X = vd[ix], Y = vd[iy];
        float p = X, pl = shl(X, lane), pr = shr(X, lane);
        #pragma unroll
        for (int i = 0; i < 4; ++i) {
            float nx = (i < 3) ? d[i + 1] : Y;
            float nl = shl(nx, lane),  nr = shr(nx, lane);
            float cl = shl(d[i], lane), cr = shr(d[i], lane);
            float v = w[i] + min8f(pl, p, pr, cl, cr, nl, nx, nr);
            if (v < d[i]) { d[i] = v; vd[i0 + i * di] = v; any = true; }
            p = d[i]; pl = shl(p, lane); pr = shr(p, lane);
        }
    }
    // backward sweep
    {
        float X = vd[ix], Y = vd[iy];
        float p = Y, pl = shl(Y, lane), pr = shr(Y, lane);
        #pragma unroll
        for (int i = 3; i >= 0; --i) {
            float nx = (i > 0) ? d[i - 1] : X;
            float nl = shl(nx, lane),  nr = shr(nx, lane);
            float cl = shl(d[i], lane), cr = shr(d[i], lane);
            float v = w[i] + min8f(nl, nx, nr, cl, cr, pl, p, pr);
            if (v < d[i]) { d[i] = v; vd[i0 + i * di] = v; any = true; }
            p = d[i]; pl = shl(p, lane); pr = shr(p, lane);
        }
    }
}

__global__ void __launch_bounds__(256, 1)
bba_kernel(const float* __restrict__ weights,
           const int*   __restrict__ source,
           const int*   __restrict__ target,
           float*       __restrict__ out)
{
    __shared__ float dist[34 * ST];     // padded 34x34, stride 35
    __shared__ float wsh[32][33];       // weights, conflict-free both axes
    __shared__ int   nbr[1024];         // backtrack linear deltas
    __shared__ int   changed;
    volatile float* vd = dist;

    const int b    = blockIdx.x;
    const int tid  = threadIdx.x;
    const int wpid = tid >> 5;          // warp id 0..7
    const int lane = tid & 31;
    const int r0   = 4 * wpid;          // V band first row
    const int c0   = 4 * wpid;          // H band first col

    // Zero poisoned output slice.
    #pragma unroll
    for (int i = 0; i < 4; ++i) out[b * 1024 + i * 256 + tid] = 0.0f;

    for (int i = tid; i < 34 * ST; i += 256) dist[i] = INF_F;

    // Weights (+EPS), V-layout load, stash in smem for H-layout reads.
    const float* wb = weights + b * 1024;
    float wv[4], wh[4];
    #pragma unroll
    for (int i = 0; i < 4; ++i) {
        wv[i] = wb[(r0 + i) * 32 + lane] + EPS_F;
        wsh[r0 + i][lane] = wv[i];
    }

    const int sr = source[2 * b + 0];
    const int sc = source[2 * b + 1];
    const int tr = target[2 * b + 0];
    const int tc = target[2 * b + 1];

    __syncthreads();

    #pragma unroll
    for (int i = 0; i < 4; ++i) wh[i] = wsh[lane][c0 + i];
    if (tid == 0) dist[(sr + 1) * ST + (sc + 1)] = wsh[sr][sc];
    __syncthreads();

    // Indices for both orientations.
    const int v_i0 = (r0 + 1) * ST + (lane + 1);   // own cells, step ST
    const int v_ix = (r0 + 0) * ST + (lane + 1);   // row above band
    const int v_iy = (r0 + 5) * ST + (lane + 1);   // row below band
    const int h_i0 = (lane + 1) * ST + (c0 + 1);   // own cells, step 1
    const int h_ix = (lane + 1) * ST + (c0 + 0);   // col left of band
    const int h_iy = (lane + 1) * ST + (c0 + 5);   // col right of band

    float d[4];

    for (;;) {
        bool any = false;

        // V phase
        #pragma unroll
        for (int i = 0; i < 4; ++i) d[i] = vd[v_i0 + i * ST];
        #pragma unroll 1
        for (int k = 0; k < KP; ++k)
            sweep_pair(vd, wv, d, v_i0, ST, v_ix, v_iy, lane, any);

        __syncthreads();                 // V writes visible to H phase

        // H phase
        #pragma unroll
        for (int i = 0; i < 4; ++i) d[i] = vd[h_i0 + i];
        #pragma unroll 1
        for (int k = 0; k < KP; ++k)
            sweep_pair(vd, wh, d, h_i0, 1, h_ix, h_iy, lane, any);

        if (any) changed = 1;            // benign race
        __syncthreads();
        int c0f = changed;
        __syncthreads();
        if (!c0f) break;                 // zero-change epoch => fixed point
        if (tid == 0) changed = 0;
        __syncthreads();
    }

    // Parallel argmin-neighbor deltas (V layout), OFFS order:
    // (-1,-1),(-1,0),(-1,1),(0,-1),(0,1),(1,-1),(1,0),(1,1)
    {
        #pragma unroll
        for (int i = 0; i < 4; ++i) d[i] = vd[v_i0 + i * ST];
        float X  = vd[v_ix], Y = vd[v_iy];
        float XL = shl(X, lane),    XR = shr(X, lane);
        float L0 = shl(d[0], lane), R0 = shr(d[0], lane);
        float L1 = shl(d[1], lane), R1 = shr(d[1], lane);
        float L2 = shl(d[2], lane), R2 = shr(d[2], lane);
        float L3 = shl(d[3], lane), R3 = shr(d[3], lane);
        float YL = shl(Y, lane),    YR = shr(Y, lane);
        nbr[(r0 + 0) * 32 + lane] = pick8d(XL, X,    XR, L0, R0, L1, d[1], R1);
        nbr[(r0 + 1) * 32 + lane] = pick8d(L0, d[0], R0, L1, R1, L2, d[2], R2);
        nbr[(r0 + 2) * 32 + lane] = pick8d(L1, d[1], R1, L2, R2, L3, d[3], R3);
        nbr[(r0 + 3) * 32 + lane] = pick8d(L2, d[2], R2, L3, R3, YL, Y,    YR);
    }
    __syncthreads();

    // Serial backtrack: idx += nbr[idx] per step (LDS + IADD chain).
    if (tid == 0) {
        int idx = (tr << 5) + tc;
        const int sidx = (sr << 5) + sc;
        float* o = out + b * 1024;
        for (int step = 0; step < 1024; ++step) {
            o[idx] = 1.0f;
            if (idx == sidx) break;
            idx += nbr[idx];
        }
    }
}

extern "C" void kernel_launch(void* const* d_in, const int* in_sizes, int n_in,
                              void* d_out, int out_size)
{
    const float* weights = (const float*)d_in[0];
    const int*   source  = (const int*)d_in[1];
    const int*   target  = (const int*)d_in[2];
    float*       out     = (float*)d_out;

    bba_kernel<<<BN, 256>>>(weights, source, target, out);
}